// round 17
// baseline (speedup 1.0000x reference)
#include <cuda_runtime.h>
#include <cstdint>

// PQLayer: x:(B,512) fp32, C:(64,256,8) fp32.
// codes == one_hot(argmax_k <x_bm, C_mk>); x_hat row == C[m,kmax,:].
// R16: interleave the codes zero-store stream INTO the argmax k-loop
// (1 STG.128 per 2 k-iters => uniform DRAM pressure instead of per-block
// compute/store phases), then scatter the single 1.0 per row afterwards.
// Removes the old sweep's kb-load/compare/branch entirely.

#define FEAT 512
#define Mn   64
#define Kn   256
#define Dn   8
#define TPB  128
#define BPT  2
#define ROWS (TPB * BPT)   // 256 b-rows per block

// ---- packed f32x2 helpers (Blackwell sm_103a; FFMA2 only via PTX) ----
__device__ __forceinline__ unsigned long long f2_mul(unsigned long long a,
                                                     unsigned long long b) {
    unsigned long long d;
    asm("mul.rn.f32x2 %0, %1, %2;" : "=l"(d) : "l"(a), "l"(b));
    return d;
}
__device__ __forceinline__ unsigned long long f2_fma(unsigned long long a,
                                                     unsigned long long b,
                                                     unsigned long long c) {
    unsigned long long d;
    asm("fma.rn.f32x2 %0, %1, %2, %3;" : "=l"(d) : "l"(a), "l"(b), "l"(c));
    return d;
}
__device__ __forceinline__ float2 f2_unpack(unsigned long long v) {
    float2 r;
    asm("mov.b64 {%0, %1}, %2;" : "=f"(r.x), "=f"(r.y) : "l"(v));
    return r;
}

// ---- streaming (evict-first) global accessors ----
__device__ __forceinline__ void ldg_cs_128(const void* p,
                                           unsigned long long& a,
                                           unsigned long long& b) {
    asm("ld.global.cs.v2.u64 {%0, %1}, [%2];" : "=l"(a), "=l"(b) : "l"(p));
}
__device__ __forceinline__ void stg_cs_128(void* p,
                                           unsigned long long a,
                                           unsigned long long b) {
    asm("st.global.cs.v2.u64 [%0], {%1, %2};" :: "l"(p), "l"(a), "l"(b));
}
__device__ __forceinline__ void stg_cs_zero4(void* p) {
    asm("st.global.cs.v4.f32 [%0], {%1, %1, %1, %1};" :: "l"(p), "f"(0.0f));
}

__global__ void __launch_bounds__(TPB, 12)
pq_kernel(const float* __restrict__ x,
          const float* __restrict__ C,
          float* __restrict__ xhat,    // may be null
          float* __restrict__ codes,   // may be null
          int nB)
{
    __shared__ ulonglong2 sC[Kn * 2];   // 8 KB codebook tile for this m

    const int m  = blockIdx.y;
    const int b0 = blockIdx.x * ROWS;
    const bool full = (b0 + ROWS) <= nB;   // B % ROWS == 0 in practice

    // Stage C[m] into smem
    const ulonglong2* Cg = reinterpret_cast<const ulonglong2*>(C + (size_t)m * Kn * Dn);
    #pragma unroll
    for (int i = threadIdx.x; i < Kn * 2; i += TPB) sC[i] = Cg[i];
    __syncthreads();

    // Load x for BPT rows (read-once stream): row t at b0 + tid + t*TPB
    unsigned long long xp[BPT][4];
    #pragma unroll
    for (int t = 0; t < BPT; ++t) {
        const int b = b0 + threadIdx.x + t * TPB;
        if (full || b < nB) {
            const char* xg = reinterpret_cast<const char*>(x + (size_t)b * FEAT + m * Dn);
            ldg_cs_128(xg,      xp[t][0], xp[t][1]);
            ldg_cs_128(xg + 16, xp[t][2], xp[t][3]);
        } else {
            xp[t][0] = xp[t][1] = xp[t][2] = xp[t][3] = 0ull;
        }
    }

    // Zero-sweep cursor: thread covers rows [r0, r0+128) consecutively at
    // fixed float4 chunk c4 = tid & 63. One store per 2 k-iterations.
    const size_t row_stride4 = (size_t)Mn * Kn / 4;
    float4* zp = nullptr;
    const bool do_inloop = (codes != nullptr) && full;
    if (codes) {
        zp = reinterpret_cast<float4*>(codes)
             + (((size_t)b0 * Mn + m) * Kn) / 4
             + (size_t)((threadIdx.x >> 6) * (ROWS / 2)) * row_stride4
             + (threadIdx.x & 63);
    }

    float best[BPT];
    int   kb[BPT];
    #pragma unroll
    for (int t = 0; t < BPT; ++t) { best[t] = -3.4e38f; kb[t] = 0; }

    // Argmax with interleaved zero stores (uniform DRAM pressure).
    #pragma unroll 4
    for (int k = 0; k < Kn; ++k) {
        const ulonglong2 c01 = sC[2 * k];
        const ulonglong2 c23 = sC[2 * k + 1];
        #pragma unroll
        for (int t = 0; t < BPT; ++t) {
            unsigned long long acc = f2_mul(xp[t][0], c01.x);
            acc = f2_fma(xp[t][1], c01.y, acc);
            acc = f2_fma(xp[t][2], c23.x, acc);
            acc = f2_fma(xp[t][3], c23.y, acc);
            float2 ab = f2_unpack(acc);
            float dot = ab.x + ab.y;
            if (dot > best[t]) { best[t] = dot; kb[t] = k; }  // strict > => first idx
        }
        if (do_inloop && (k & 1) == 0) {       // 128 stores across 256 iters
            stg_cs_zero4(zp);
            zp += row_stride4;
        }
    }

    // x_hat rows straight from the smem codebook (streaming store)
    if (xhat) {
        #pragma unroll
        for (int t = 0; t < BPT; ++t) {
            const int b = b0 + threadIdx.x + t * TPB;
            if (full || b < nB) {
                char* o = reinterpret_cast<char*>(xhat + (size_t)b * FEAT + m * Dn);
                ulonglong2 v0 = sC[2 * kb[t]];
                ulonglong2 v1 = sC[2 * kb[t] + 1];
                stg_cs_128(o,      v0.x, v0.y);
                stg_cs_128(o + 16, v1.x, v1.y);
            }
        }
    }

    if (codes) {
        if (full) {
            // Order: zeros (written by other threads) before this thread's 1.0s.
            // __syncthreads gives CTA-scope ordering + visibility for global.
            __syncthreads();
            #pragma unroll
            for (int t = 0; t < BPT; ++t) {
                const int b = b0 + threadIdx.x + t * TPB;
                codes[(size_t)b * Mn * Kn + (size_t)m * Kn + kb[t]] = 1.0f;
            }
        } else {
            // Rare partial block: each thread writes its own rows completely.
            #pragma unroll
            for (int t = 0; t < BPT; ++t) {
                const int b = b0 + threadIdx.x + t * TPB;
                if (b >= nB) continue;
                float* row = codes + (size_t)b * Mn * Kn + (size_t)m * Kn;
                #pragma unroll 8
                for (int c = 0; c < Kn; ++c) row[c] = 0.0f;
                row[kb[t]] = 1.0f;
            }
        }
    }
}

extern "C" void kernel_launch(void* const* d_in, const int* in_sizes, int n_in,
                              void* d_out, int out_size)
{
    // Resolve inputs by size: x has B*512 elems, C has 64*256*8 = 131072 elems.
    const float* x = (const float*)d_in[0];
    const float* C = (const float*)d_in[1];
    int x_size = in_sizes[0];
    if (n_in >= 2 && in_sizes[0] == Mn * Kn * Dn && in_sizes[1] != Mn * Kn * Dn) {
        x = (const float*)d_in[1];
        C = (const float*)d_in[0];
        x_size = in_sizes[1];
    }
    const int nB = x_size / FEAT;

    const long long XH = (long long)nB * FEAT;        // x_hat elems
    const long long CD = (long long)nB * Mn * Kn;     // codes elems

    float* out   = (float*)d_out;
    float* xhat  = nullptr;
    float* codes = nullptr;
    if ((long long)out_size == XH + CD)      { xhat = out; codes = out + XH; }
    else if ((long long)out_size == XH)      { xhat = out; }
    else if ((long long)out_size == CD)      { codes = out; }
    else                                     { xhat = out; codes = out + XH; }

    dim3 grid((nB + ROWS - 1) / ROWS, Mn);
    pq_kernel<<<grid, TPB>>>(x, C, xhat, codes, nB);
}